// round 7
// baseline (speedup 1.0000x reference)
#include <cuda_runtime.h>

#define BB 4
#define NN 16384
#define NC 1024

// ---------------- scratch (device globals; no allocation allowed) ----------------
__device__ unsigned int g_flagbits[BB][NN / 32];
__device__ int          g_list[BB][NN];
__device__ int          g_list_cnt[BB];
__device__ float        g_feat[BB * 1024];           // max-pooled (relu'd) features
__device__ float        g_a1[BB][512];               // fc layer-1 activations
__device__ float        g_h4[BB][NN][128];           // per-point layer-4 activations
__device__ float        g_tw1[3 * 64];               // transposed small weights
__device__ float        g_tw2[64 * 64];
__device__ float        g_tw3[64 * 64];
__device__ float        g_tw4[64 * 128];
__device__ float        g_w5t[128 * 1024];           // transposed w5: [k][o]

// ---------------- helpers ----------------
__device__ __forceinline__ unsigned long long dkey(float d, int idx) {
    unsigned u = __float_as_uint(d);
    u = (u & 0x80000000u) ? ~u : (u | 0x80000000u);   // ascending-sortable
    return ((unsigned long long)u << 32) | (unsigned)idx;
}

__device__ __forceinline__ void warp_max(unsigned long long key, int lane,
                                         unsigned long long& mk, int& ml) {
    unsigned long long v = key; int l = lane;
    #pragma unroll
    for (int off = 16; off; off >>= 1) {
        unsigned long long v2 = __shfl_xor_sync(0xffffffffu, v, off);
        int l2 = __shfl_xor_sync(0xffffffffu, l, off);
        if (v2 > v) { v = v2; l = l2; }
    }
    mk = v; ml = l;
}

__device__ __forceinline__ float warp_sum(float s) {
    #pragma unroll
    for (int off = 16; off; off >>= 1)
        s += __shfl_xor_sync(0xffffffffu, s, off);
    return s;
}

// ---------------- prep: tiled w5 transpose (blocks 0-127) + zero/small (128-159) --
__global__ __launch_bounds__(256) void prep_kernel(
    const float* __restrict__ w1, const float* __restrict__ w2,
    const float* __restrict__ w3, const float* __restrict__ w4,
    const float* __restrict__ w5) {
    const int t = threadIdx.x;
    if (blockIdx.x < 128) {
        // 32x32 tile transpose of w5 [1024 x 128] -> g_w5t [128 x 1024]
        __shared__ float tile[32][33];
        const int k0 = (blockIdx.x & 3) * 32;
        const int o0 = (blockIdx.x >> 2) * 32;
        const int tx = t & 31, ty = t >> 5;
        #pragma unroll
        for (int r = ty; r < 32; r += 8)
            tile[r][tx] = w5[(o0 + r) * 128 + k0 + tx];     // coalesced read
        __syncthreads();
        #pragma unroll
        for (int r = ty; r < 32; r += 8)
            g_w5t[(k0 + r) * 1024 + o0 + tx] = tile[tx][r]; // coalesced write
    } else {
        int i = (blockIdx.x - 128) * 256 + t;               // 0..8191
        if (i < BB * NN / 32) ((unsigned*)g_flagbits)[i] = 0u;
        if (i < BB * 1024)    g_feat[i] = 0.0f;
        if (i < BB)           g_list_cnt[i] = 0;
        if (i < 192)  { int o = i % 64, k = i / 64;  g_tw1[k * 64 + o]  = w1[o * 3 + k]; }
        if (i < 4096) { int o = i & 63, k = i >> 6;  g_tw2[k * 64 + o]  = w2[o * 64 + k];
                                                     g_tw3[k * 64 + o]  = w3[o * 64 + k]; }
        if (i < 8192) { int o = i & 127, k = i >> 7; g_tw4[k * 128 + o] = w4[o * 64 + k]; }
    }
}

// ---------------- fused FPS walk + exact top-32 KNN + dedup list append -----------
__global__ __launch_bounds__(1024) void fpsknn_kernel(const float* __restrict__ x,
                                                      const int* __restrict__ far_init) {
    extern __shared__ float dsm[];
    float* sx = dsm;
    float* sy = sx + NN;
    float* sz = sy + NN;
    unsigned long long* cand = (unsigned long long*)(sz + NN);
    __shared__ unsigned s_seen[NN / 32];
    __shared__ int s_cent[NC];
    __shared__ float s_d[32];
    __shared__ int   s_i[32];
    __shared__ int   s_far, s_stop, s_cnt;

    const int b = blockIdx.x >> 3, m0 = blockIdx.x & 7;
    const float* xb = x + (size_t)b * NN * 3;
    const int t = threadIdx.x, w = t >> 5, lane = t & 31;

    #pragma unroll
    for (int j = 0; j < 16; ++j) {
        const int i = t + j * 1024;
        sx[i] = xb[i * 3 + 0]; sy[i] = xb[i * 3 + 1]; sz[i] = xb[i * 3 + 2];
    }
    if (t < NN / 32) s_seen[t] = 0;
    if (t == 0) s_cnt = 0;
    __syncthreads();

    // ---- FPS walk with cycle detection ----
    int far = far_init[b];
    for (int it = 0; it < NC; ++it) {
        if (t == 0) {
            const unsigned wd = (unsigned)far >> 5, bt = 1u << (far & 31);
            if (s_seen[wd] & bt) { s_stop = 1; }
            else { s_seen[wd] |= bt; s_cent[s_cnt++] = far; s_stop = 0; }
        }
        __syncthreads();
        if (s_stop) break;
        if (it == NC - 1) break;

        const float cx = sx[far], cy = sy[far], cz = sz[far];
        float best = -1.0f; int bi = 0;
        #pragma unroll
        for (int j = 0; j < 16; ++j) {
            const int i = t + j * 1024;
            float dx = sx[i] - cx, dy = sy[i] - cy, dz = sz[i] - cz;
            float d = dx * dx + dy * dy + dz * dz;
            if (d > best) { best = d; bi = i; }   // strict >: lowest idx on tie
        }
        #pragma unroll
        for (int off = 16; off; off >>= 1) {
            float d2 = __shfl_xor_sync(0xffffffffu, best, off);
            int   i2 = __shfl_xor_sync(0xffffffffu, bi, off);
            if (d2 > best || (d2 == best && i2 < bi)) { best = d2; bi = i2; }
        }
        if (lane == 0) { s_d[w] = best; s_i[w] = bi; }
        __syncthreads();
        if (t < 32) {
            best = s_d[t]; bi = s_i[t];
            #pragma unroll
            for (int off = 16; off; off >>= 1) {
                float d2 = __shfl_xor_sync(0xffffffffu, best, off);
                int   i2 = __shfl_xor_sync(0xffffffffu, bi, off);
                if (d2 > best || (d2 == best && i2 < bi)) { best = d2; bi = i2; }
            }
            if (t == 0) s_far = bi;
        }
        __syncthreads();
        far = s_far;
    }
    __syncthreads();

    // ---- exact top-32 KNN from smem SoA, 32 warps per centroid ----
    const int cnt = s_cnt;
    for (int m = m0; m < cnt; m += 8) {
        const int ci = s_cent[m];
        const float cx = sx[ci], cy = sy[ci], cz = sz[ci];
        const float cn = cx * cx + cy * cy + cz * cz;
        const int base = w * 512;

        unsigned long long key;
        {
            const int p = base + lane;
            float px = sx[p], py = sy[p], pz = sz[p];
            float xn = px * px + py * py + pz * pz;
            float dot = cx * px + cy * py + cz * pz;
            key = dkey((cn + xn) - 2.0f * dot, p);
        }
        unsigned long long mk; int ml;
        warp_max(key, lane, mk, ml);

        for (int off = 32; off < 512; off += 32) {
            const int p = base + off + lane;
            float px = sx[p], py = sy[p], pz = sz[p];
            float xn = px * px + py * py + pz * pz;
            float dot = cx * px + cy * py + cz * pz;
            unsigned long long k = dkey((cn + xn) - 2.0f * dot, p);
            unsigned mask = __ballot_sync(0xffffffffu, k < mk);
            while (mask) {
                const int src = __ffs(mask) - 1;
                mask &= mask - 1;
                unsigned long long kc = __shfl_sync(0xffffffffu, k, src);
                if (kc < mk) {
                    if (lane == ml) key = kc;
                    warp_max(key, lane, mk, ml);
                }
            }
        }
        cand[t] = key;
        __syncthreads();

        if (w == 0) {                       // exact merge of 1024 candidates
            key = cand[lane];
            warp_max(key, lane, mk, ml);
            for (int c = 32; c < 1024; c += 32) {
                unsigned long long k = cand[c + lane];
                unsigned mask = __ballot_sync(0xffffffffu, k < mk);
                while (mask) {
                    const int src = __ffs(mask) - 1;
                    mask &= mask - 1;
                    unsigned long long kc = __shfl_sync(0xffffffffu, k, src);
                    if (kc < mk) {
                        if (lane == ml) key = kc;
                        warp_max(key, lane, mk, ml);
                    }
                }
            }
            // dedup append to union list
            const int n = (int)(key & 0xffffffffull);
            const unsigned bt = 1u << (n & 31);
            unsigned old = atomicOr(&g_flagbits[b][(unsigned)n >> 5], bt);
            if (!(old & bt)) {
                int pos = atomicAdd(&g_list_cnt[b], 1);
                g_list[b][pos] = n;
            }
        }
        __syncthreads();
    }
}

// ---------------- chain: 3->64->64->64->128 per point, ONE WARP PER POINT ---------
__global__ __launch_bounds__(256) void chain_kernel(
    const float* __restrict__ x,
    const float* __restrict__ b1, const float* __restrict__ b2,
    const float* __restrict__ b3, const float* __restrict__ b4) {
    const int b = blockIdx.x >> 4, blk = blockIdx.x & 15;
    const int t = threadIdx.x, w = t >> 5, lane = t & 31;
    const int cnt = g_list_cnt[b];
    __shared__ float sh[8][64];

    for (int i = blk * 8 + w; i < cnt; i += 128) {
        const int n = g_list[b][i];
        const float* pp = x + ((size_t)b * NN + n) * 3;
        const float px = pp[0], py = pp[1], pz = pp[2];
        const int oA = lane, oB = lane + 32;

        // L1: 3 -> 64
        {
            float a = b1[oA] + g_tw1[oA] * px + g_tw1[64 + oA] * py + g_tw1[128 + oA] * pz;
            float c = b1[oB] + g_tw1[oB] * px + g_tw1[64 + oB] * py + g_tw1[128 + oB] * pz;
            sh[w][oA] = fmaxf(a, 0.0f);
            sh[w][oB] = fmaxf(c, 0.0f);
        }
        __syncwarp();
        // L2: 64 -> 64
        {
            float A0 = 0.f, A1 = 0.f, A2 = 0.f, A3 = 0.f;
            float B0 = 0.f, B1 = 0.f, B2 = 0.f, B3 = 0.f;
            #pragma unroll
            for (int k = 0; k < 64; k += 4) {
                float h0 = sh[w][k], h1 = sh[w][k + 1], h2 = sh[w][k + 2], h3 = sh[w][k + 3];
                A0 += g_tw2[(k + 0) * 64 + oA] * h0; A1 += g_tw2[(k + 1) * 64 + oA] * h1;
                A2 += g_tw2[(k + 2) * 64 + oA] * h2; A3 += g_tw2[(k + 3) * 64 + oA] * h3;
                B0 += g_tw2[(k + 0) * 64 + oB] * h0; B1 += g_tw2[(k + 1) * 64 + oB] * h1;
                B2 += g_tw2[(k + 2) * 64 + oB] * h2; B3 += g_tw2[(k + 3) * 64 + oB] * h3;
            }
            float ha = fmaxf(b2[oA] + ((A0 + A1) + (A2 + A3)), 0.0f);
            float hb = fmaxf(b2[oB] + ((B0 + B1) + (B2 + B3)), 0.0f);
            __syncwarp();
            sh[w][oA] = ha; sh[w][oB] = hb;
        }
        __syncwarp();
        // L3: 64 -> 64
        {
            float A0 = 0.f, A1 = 0.f, A2 = 0.f, A3 = 0.f;
            float B0 = 0.f, B1 = 0.f, B2 = 0.f, B3 = 0.f;
            #pragma unroll
            for (int k = 0; k < 64; k += 4) {
                float h0 = sh[w][k], h1 = sh[w][k + 1], h2 = sh[w][k + 2], h3 = sh[w][k + 3];
                A0 += g_tw3[(k + 0) * 64 + oA] * h0; A1 += g_tw3[(k + 1) * 64 + oA] * h1;
                A2 += g_tw3[(k + 2) * 64 + oA] * h2; A3 += g_tw3[(k + 3) * 64 + oA] * h3;
                B0 += g_tw3[(k + 0) * 64 + oB] * h0; B1 += g_tw3[(k + 1) * 64 + oB] * h1;
                B2 += g_tw3[(k + 2) * 64 + oB] * h2; B3 += g_tw3[(k + 3) * 64 + oB] * h3;
            }
            float ha = fmaxf(b3[oA] + ((A0 + A1) + (A2 + A3)), 0.0f);
            float hb = fmaxf(b3[oB] + ((B0 + B1) + (B2 + B3)), 0.0f);
            __syncwarp();
            sh[w][oA] = ha; sh[w][oB] = hb;
        }
        __syncwarp();
        // L4: 64 -> 128, write to g_h4
        {
            float acc[4][4];
            #pragma unroll
            for (int j = 0; j < 4; ++j)
                #pragma unroll
                for (int u = 0; u < 4; ++u) acc[j][u] = 0.f;
            #pragma unroll
            for (int k = 0; k < 64; k += 4) {
                float hv[4] = {sh[w][k], sh[w][k + 1], sh[w][k + 2], sh[w][k + 3]};
                #pragma unroll
                for (int j = 0; j < 4; ++j) {
                    const int o = lane + 32 * j;
                    #pragma unroll
                    for (int u = 0; u < 4; ++u)
                        acc[j][u] += g_tw4[(k + u) * 128 + o] * hv[u];
                }
            }
            #pragma unroll
            for (int j = 0; j < 4; ++j) {
                const int o = lane + 32 * j;
                g_h4[b][i][o] = fmaxf(b4[o] + ((acc[j][0] + acc[j][1]) + (acc[j][2] + acc[j][3])), 0.0f);
            }
        }
        __syncwarp();
    }
}

// ---------------- pool: w5t x h4 + relu + maxpool, 1 output/thread, 16 pts --------
#define PT 16
__global__ __launch_bounds__(256) void pool_kernel(const float* __restrict__ b5) {
    const int bid = blockIdx.x;           // BB * 4 quarters * 8 slots = 128
    const int b = bid >> 5, q = (bid >> 3) & 3, slot = bid & 7;
    const int t = threadIdx.x;
    const int o = q * 256 + t;
    __shared__ float hs[PT][128];
    const int cnt = g_list_cnt[b];
    const float bias = b5[o];
    float rmax = 0.0f;

    for (int i0 = slot * PT; i0 < cnt; i0 += 8 * PT) {
        const int rem = min(PT, cnt - i0);
        __syncthreads();
        #pragma unroll
        for (int j = 0; j < 8; ++j) {
            const int idx = t + j * 256;
            const int p = idx >> 7, k = idx & 127;
            hs[p][k] = (p < rem) ? g_h4[b][i0 + p][k] : 0.0f;
        }
        __syncthreads();
        float acc[PT];
        #pragma unroll
        for (int p = 0; p < PT; ++p) acc[p] = 0.0f;
        #pragma unroll 4
        for (int k = 0; k < 128; ++k) {
            const float wv = g_w5t[k * 1024 + o];
            #pragma unroll
            for (int p = 0; p < PT; ++p) acc[p] += wv * hs[p][k];
        }
        for (int p = 0; p < rem; ++p)
            rmax = fmaxf(rmax, fmaxf(acc[p] + bias, 0.0f));
    }
    atomicMax((unsigned int*)&g_feat[b * 1024 + o], __float_as_uint(rmax));
}

// ---------------- FC layer 1 (1024->512), one output per warp ---------------------
__global__ __launch_bounds__(256) void fc1_kernel(const float* __restrict__ fw1,
                                                  const float* __restrict__ fb1) {
    const int b = blockIdx.x >> 6, seg = blockIdx.x & 63;
    __shared__ __align__(16) float g[1024];
    const int t = threadIdx.x, w = t >> 5, lane = t & 31;

    for (int i = t; i < 1024; i += 256) g[i] = g_feat[b * 1024 + i];
    __syncthreads();

    const int o = seg * 8 + w;
    const float4* wr = (const float4*)(fw1 + o * 1024);
    float s = 0.0f;
    #pragma unroll
    for (int it = 0; it < 8; ++it) {
        float4 wv = wr[it * 32 + lane];
        float4 gv = *(const float4*)(g + it * 128 + lane * 4);
        s += wv.x * gv.x + wv.y * gv.y + wv.z * gv.z + wv.w * gv.w;
    }
    s = warp_sum(s);
    if (lane == 0) g_a1[b][o] = fmaxf(s + fb1[o], 0.0f);
}

// ---------------- FC layers 2+3 (512->256->3), 1 block per batch ------------------
__global__ __launch_bounds__(512) void fc2_kernel(
    const float* __restrict__ fw2, const float* __restrict__ fb2,
    const float* __restrict__ fw3, const float* __restrict__ fb3,
    float* __restrict__ out) {
    const int b = blockIdx.x;
    __shared__ __align__(16) float a1[512];
    __shared__ __align__(16) float a2[256];
    const int t = threadIdx.x, w = t >> 5, lane = t & 31;

    a1[t] = g_a1[b][t];
    __syncthreads();

    {
        const int o = w * 16;   // 16 warps x 16 outputs
        for (int j = 0; j < 16; ++j) {
            const float4* wr = (const float4*)(fw2 + (o + j) * 512);
            float s = 0.0f;
            #pragma unroll
            for (int it = 0; it < 4; ++it) {
                float4 wv = wr[it * 32 + lane];
                float4 av = *(const float4*)(a1 + it * 128 + lane * 4);
                s += wv.x * av.x + wv.y * av.y + wv.z * av.z + wv.w * av.w;
            }
            s = warp_sum(s);
            if (lane == 0) a2[o + j] = fmaxf(s + fb2[o + j], 0.0f);
        }
    }
    __syncthreads();

    if (w < 3) {
        const float4* wr = (const float4*)(fw3 + w * 256);
        float s = 0.0f;
        #pragma unroll
        for (int it = 0; it < 2; ++it) {
            float4 wv = wr[it * 32 + lane];
            float4 av = *(const float4*)(a2 + it * 128 + lane * 4);
            s += wv.x * av.x + wv.y * av.y + wv.z * av.z + wv.w * av.w;
        }
        s = warp_sum(s);
        if (lane == 0) out[b * 3 + w] = s + fb3[w];
    }
}

// ---------------- launch ----------------
extern "C" void kernel_launch(void* const* d_in, const int* in_sizes, int n_in,
                              void* d_out, int out_size) {
    const float* x   = (const float*)d_in[0];
    const int*   far = (const int*)  d_in[1];
    const float* w1 = (const float*)d_in[2];   const float* b1 = (const float*)d_in[3];
    const float* w2 = (const float*)d_in[4];   const float* b2 = (const float*)d_in[5];
    const float* w3 = (const float*)d_in[6];   const float* b3 = (const float*)d_in[7];
    const float* w4 = (const float*)d_in[8];   const float* b4 = (const float*)d_in[9];
    const float* w5 = (const float*)d_in[10];  const float* b5 = (const float*)d_in[11];
    const float* fw1 = (const float*)d_in[12]; const float* fb1 = (const float*)d_in[13];
    const float* fw2 = (const float*)d_in[14]; const float* fb2 = (const float*)d_in[15];
    const float* fw3 = (const float*)d_in[16]; const float* fb3 = (const float*)d_in[17];
    float* out = (float*)d_out;

    const int smem_bytes = 3 * NN * 4 + 1024 * 8;   // SoA + merge candidates = 204800
    static int attr_set = 0;
    if (!attr_set) {
        cudaFuncSetAttribute(fpsknn_kernel,
                             cudaFuncAttributeMaxDynamicSharedMemorySize, smem_bytes);
        attr_set = 1;
    }

    prep_kernel<<<160, 256>>>(w1, w2, w3, w4, w5);
    fpsknn_kernel<<<BB * 8, 1024, smem_bytes>>>(x, far);
    chain_kernel<<<BB * 16, 256>>>(x, b1, b2, b3, b4);
    pool_kernel<<<BB * 32, 256>>>(b5);
    fc1_kernel<<<BB * 64, 256>>>(fw1, fb1);
    fc2_kernel<<<BB, 512>>>(fw2, fb2, fw3, fb3, out);
}

// round 8
// speedup vs baseline: 1.6307x; 1.6307x over previous
#include <cuda_runtime.h>

#define BB 4
#define NN 16384
#define NC 1024

// ---------------- scratch (device globals; no allocation allowed) ----------------
__device__ unsigned int g_flagbits[BB][NN / 32];
__device__ int          g_list[BB][NN];
__device__ int          g_list_cnt[BB];
__device__ float        g_feat[BB * 1024];           // max-pooled (relu'd) features
__device__ float        g_a1[BB][512];               // fc layer-1 activations
__device__ float        g_h4[BB][NN][128];           // per-point layer-4 activations
__device__ float        g_tw1[3 * 64];               // transposed small weights
__device__ float        g_tw2[64 * 64];
__device__ float        g_tw3[64 * 64];
__device__ float        g_tw4[64 * 128];

// ---------------- helpers ----------------
__device__ __forceinline__ unsigned sortable(float d) {
    unsigned u = __float_as_uint(d);
    return (u & 0x80000000u) ? ~u : (u | 0x80000000u);   // ascending-sortable
}

__device__ __forceinline__ float warp_sum(float s) {
    #pragma unroll
    for (int off = 16; off; off >>= 1)
        s += __shfl_xor_sync(0xffffffffu, s, off);
    return s;
}

__device__ __forceinline__ unsigned long long u64max_bfly(unsigned long long v) {
    #pragma unroll
    for (int off = 16; off; off >>= 1) {
        unsigned long long v2 = __shfl_xor_sync(0xffffffffu, v, off);
        if (v2 > v) v = v2;
    }
    return v;
}

__device__ __forceinline__ void ffma2(unsigned long long& acc, unsigned long long a,
                                      unsigned long long b) {
    asm("fma.rn.f32x2 %0, %1, %2, %0;" : "+l"(acc) : "l"(a), "l"(b));
}

// ---------------- prep: zero scratch + transpose small weights --------------------
__global__ __launch_bounds__(256) void prep_kernel(
    const float* __restrict__ w1, const float* __restrict__ w2,
    const float* __restrict__ w3, const float* __restrict__ w4) {
    int i = blockIdx.x * 256 + threadIdx.x;             // 8192 threads
    if (i < BB * NN / 32) ((unsigned*)g_flagbits)[i] = 0u;
    if (i < BB * 1024)    g_feat[i] = 0.0f;
    if (i < BB)           g_list_cnt[i] = 0;
    if (i < 192)  { int o = i % 64, k = i / 64;  g_tw1[k * 64 + o]  = w1[o * 3 + k]; }
    if (i < 4096) { int o = i & 63, k = i >> 6;  g_tw2[k * 64 + o]  = w2[o * 64 + k];
                                                 g_tw3[k * 64 + o]  = w3[o * 64 + k]; }
    if (i < 8192) { int o = i & 127, k = i >> 7; g_tw4[k * 128 + o] = w4[o * 64 + k]; }
}

// ---------------- fused FPS walk + exact radix top-32 KNN + dedup append ----------
// BB*16 blocks of 1024. Each block stages its batch into smem SoA + registers,
// redundantly runs the serial FPS walk, then handles centroids m0, m0+16, ...
__global__ __launch_bounds__(1024) void fpsknn_kernel(const float* __restrict__ x,
                                                      const int* __restrict__ far_init) {
    extern __shared__ float dsm[];
    float* sx = dsm;
    float* sy = sx + NN;
    float* sz = sy + NN;
    unsigned long long* cand = (unsigned long long*)(sz + NN);
    __shared__ unsigned long long s_pack[32];
    __shared__ unsigned s_seen[NN / 32];
    __shared__ int s_cent[NC];
    __shared__ int s_stop, s_cnt;
    __shared__ unsigned s_minidx;

    const int b = blockIdx.x >> 4, m0 = blockIdx.x & 15;
    const float* xb = x + (size_t)b * NN * 3;
    const int t = threadIdx.x, w = t >> 5, lane = t & 31;
    const unsigned lmask_lt = (1u << lane) - 1u;

    float rx[16], ry[16], rz[16];
    #pragma unroll
    for (int j = 0; j < 16; ++j) {
        const int i = t + j * 1024;
        float a = xb[i * 3 + 0], bv = xb[i * 3 + 1], c = xb[i * 3 + 2];
        sx[i] = a; sy[i] = bv; sz[i] = c;
        rx[j] = a; ry[j] = bv; rz[j] = c;
    }
    if (t < NN / 32) s_seen[t] = 0;
    if (t == 0) s_cnt = 0;
    __syncthreads();

    // ---- FPS walk with cycle detection (points in registers, 2 BARs/iter) ----
    int far = far_init[b];
    for (int it = 0; it < NC; ++it) {
        if (t == 0) {
            const unsigned wd = (unsigned)far >> 5, bt = 1u << (far & 31);
            if (s_seen[wd] & bt) { s_stop = 1; }
            else { s_seen[wd] |= bt; s_cent[s_cnt++] = far; s_stop = 0; }
        }
        __syncthreads();
        if (s_stop) break;
        if (it == NC - 1) break;

        const float cx = sx[far], cy = sy[far], cz = sz[far];
        float best = -1.0f; int bi = 0;
        #pragma unroll
        for (int j = 0; j < 16; ++j) {
            float dx = rx[j] - cx, dy = ry[j] - cy, dz = rz[j] - cz;
            float d = dx * dx + dy * dy + dz * dz;
            if (d > best) { best = d; bi = t + j * 1024; }   // strict >: lowest idx on tie
        }
        // pack (dist asc, then smaller idx wins): d >= 0 so raw bits are ordered
        unsigned long long pk = ((unsigned long long)__float_as_uint(best) << 32)
                              | (unsigned)(~bi);
        pk = u64max_bfly(pk);
        if (lane == 0) s_pack[w] = pk;
        __syncthreads();
        unsigned long long v = s_pack[lane];
        v = u64max_bfly(v);                  // every warp redundantly; all lanes get max
        far = (int)(~(unsigned)v);
    }
    __syncthreads();

    // ---- exact top-32 KNN via two-level radix select ----
    const int cnt = s_cnt;
    for (int m = m0; m < cnt; m += 16) {
        const int ci = s_cent[m];
        const float cx = sx[ci], cy = sy[ci], cz = sz[ci];
        const float cn = cx * cx + cy * cy + cz * cz;
        const int base = w * 512;

        // per-lane 16 sortable distance keys (points base + j*32 + lane)
        unsigned ds[16];
        #pragma unroll
        for (int j = 0; j < 16; ++j) {
            const int p = base + j * 32 + lane;
            float px = sx[p], py = sy[p], pz = sz[p];
            float xn = px * px + py * py + pz * pz;
            float dot = cx * px + cy * py + cz * pz;
            ds[j] = sortable((cn + xn) - 2.0f * dot);
        }

        // warp-level radix-descend: value T of the 32nd smallest among 512
        unsigned pfx = 0; int kth = 32;
        for (int bit = 31; bit >= 0; --bit) {
            const unsigned tgt = pfx << 1;
            int c = 0;
            #pragma unroll
            for (int j = 0; j < 16; ++j) c += ((ds[j] >> bit) == tgt);
            const int tot = __reduce_add_sync(0xffffffffu, c);
            if (kth <= tot) pfx = tgt; else { kth -= tot; pfx = tgt + 1; }
        }
        const unsigned T = pfx;

        // select: all < T, plus (32 - L) of == T by smallest index
        unsigned selbits = 0;
        int cl = 0;
        #pragma unroll
        for (int j = 0; j < 16; ++j) {
            if (ds[j] < T) { selbits |= 1u << j; ++cl; }
        }
        int mtake = 32 - __reduce_add_sync(0xffffffffu, cl);
        while (mtake > 0) {
            unsigned me = 0xffffffffu; int jmin = -1;
            #pragma unroll
            for (int j = 0; j < 16; ++j) {
                if (ds[j] == T && !((selbits >> j) & 1u)) {
                    unsigned pid = (unsigned)(base + j * 32 + lane);
                    if (pid < me) { me = pid; jmin = j; }
                }
            }
            const unsigned gmin = __reduce_min_sync(0xffffffffu, me);
            if (me == gmin && jmin >= 0) selbits |= 1u << jmin;
            --mtake;
        }

        // compact exactly 32 (key,idx) entries into cand[w*32 ..]
        int off = 0;
        #pragma unroll
        for (int j = 0; j < 16; ++j) {
            const bool s = (selbits >> j) & 1u;
            const unsigned msk = __ballot_sync(0xffffffffu, s);
            if (s) {
                const int pos = off + __popc(msk & lmask_lt);
                cand[w * 32 + pos] = ((unsigned long long)ds[j] << 32)
                                   | (unsigned)(base + j * 32 + lane);
            }
            off += __popc(msk);
        }
        __syncthreads();

        // block-level radix-descend over the 1024 candidates (1 per thread)
        const unsigned long long ck = cand[t];
        const unsigned cd = (unsigned)(ck >> 32);
        const unsigned cidx = (unsigned)ck;
        unsigned qfx = 0; int kb = 32;
        for (int bit = 31; bit >= 0; --bit) {
            const unsigned tgt = qfx << 1;
            const int c1 = __syncthreads_count((cd >> bit) == tgt);
            if (kb <= c1) qfx = tgt; else { kb -= c1; qfx = tgt + 1; }
        }
        const unsigned Tb = qfx;
        const int Lb = __syncthreads_count(cd < Tb);
        int mtk = 32 - Lb;
        bool takeme = (cd < Tb);
        while (mtk > 0) {
            if (t == 0) s_minidx = 0xffffffffu;
            __syncthreads();
            if (cd == Tb && !takeme) atomicMin(&s_minidx, cidx);
            __syncthreads();
            if (cd == Tb && !takeme && cidx == s_minidx) takeme = true;
            --mtk;
            __syncthreads();
        }
        if (takeme) {
            const int n = (int)cidx;
            const unsigned bt = 1u << (n & 31);
            unsigned old = atomicOr(&g_flagbits[b][(unsigned)n >> 5], bt);
            if (!(old & bt)) {
                int pos = atomicAdd(&g_list_cnt[b], 1);
                g_list[b][pos] = n;
            }
        }
        __syncthreads();   // protect cand before next centroid
    }
}

// ---------------- chain: 3->64->64->64->128 per point, ONE WARP PER POINT ---------
__global__ __launch_bounds__(256) void chain_kernel(
    const float* __restrict__ x,
    const float* __restrict__ b1, const float* __restrict__ b2,
    const float* __restrict__ b3, const float* __restrict__ b4) {
    const int b = blockIdx.x >> 4, blk = blockIdx.x & 15;
    const int t = threadIdx.x, w = t >> 5, lane = t & 31;
    const int cnt = g_list_cnt[b];
    __shared__ float sh[8][64];

    for (int i = blk * 8 + w; i < cnt; i += 128) {
        const int n = g_list[b][i];
        const float* pp = x + ((size_t)b * NN + n) * 3;
        const float px = pp[0], py = pp[1], pz = pp[2];
        const int oA = lane, oB = lane + 32;

        {
            float a = b1[oA] + g_tw1[oA] * px + g_tw1[64 + oA] * py + g_tw1[128 + oA] * pz;
            float c = b1[oB] + g_tw1[oB] * px + g_tw1[64 + oB] * py + g_tw1[128 + oB] * pz;
            sh[w][oA] = fmaxf(a, 0.0f);
            sh[w][oB] = fmaxf(c, 0.0f);
        }
        __syncwarp();
        {
            float A0 = 0.f, A1 = 0.f, A2 = 0.f, A3 = 0.f;
            float B0 = 0.f, B1 = 0.f, B2 = 0.f, B3 = 0.f;
            #pragma unroll
            for (int k = 0; k < 64; k += 4) {
                float h0 = sh[w][k], h1 = sh[w][k + 1], h2 = sh[w][k + 2], h3 = sh[w][k + 3];
                A0 += g_tw2[(k + 0) * 64 + oA] * h0; A1 += g_tw2[(k + 1) * 64 + oA] * h1;
                A2 += g_tw2[(k + 2) * 64 + oA] * h2; A3 += g_tw2[(k + 3) * 64 + oA] * h3;
                B0 += g_tw2[(k + 0) * 64 + oB] * h0; B1 += g_tw2[(k + 1) * 64 + oB] * h1;
                B2 += g_tw2[(k + 2) * 64 + oB] * h2; B3 += g_tw2[(k + 3) * 64 + oB] * h3;
            }
            float ha = fmaxf(b2[oA] + ((A0 + A1) + (A2 + A3)), 0.0f);
            float hb = fmaxf(b2[oB] + ((B0 + B1) + (B2 + B3)), 0.0f);
            __syncwarp();
            sh[w][oA] = ha; sh[w][oB] = hb;
        }
        __syncwarp();
        {
            float A0 = 0.f, A1 = 0.f, A2 = 0.f, A3 = 0.f;
            float B0 = 0.f, B1 = 0.f, B2 = 0.f, B3 = 0.f;
            #pragma unroll
            for (int k = 0; k < 64; k += 4) {
                float h0 = sh[w][k], h1 = sh[w][k + 1], h2 = sh[w][k + 2], h3 = sh[w][k + 3];
                A0 += g_tw3[(k + 0) * 64 + oA] * h0; A1 += g_tw3[(k + 1) * 64 + oA] * h1;
                A2 += g_tw3[(k + 2) * 64 + oA] * h2; A3 += g_tw3[(k + 3) * 64 + oA] * h3;
                B0 += g_tw3[(k + 0) * 64 + oB] * h0; B1 += g_tw3[(k + 1) * 64 + oB] * h1;
                B2 += g_tw3[(k + 2) * 64 + oB] * h2; B3 += g_tw3[(k + 3) * 64 + oB] * h3;
            }
            float ha = fmaxf(b3[oA] + ((A0 + A1) + (A2 + A3)), 0.0f);
            float hb = fmaxf(b3[oB] + ((B0 + B1) + (B2 + B3)), 0.0f);
            __syncwarp();
            sh[w][oA] = ha; sh[w][oB] = hb;
        }
        __syncwarp();
        {
            float acc[4][4];
            #pragma unroll
            for (int j = 0; j < 4; ++j)
                #pragma unroll
                for (int u = 0; u < 4; ++u) acc[j][u] = 0.f;
            #pragma unroll
            for (int k = 0; k < 64; k += 4) {
                float hv[4] = {sh[w][k], sh[w][k + 1], sh[w][k + 2], sh[w][k + 3]};
                #pragma unroll
                for (int j = 0; j < 4; ++j) {
                    const int o = lane + 32 * j;
                    #pragma unroll
                    for (int u = 0; u < 4; ++u)
                        acc[j][u] += g_tw4[(k + u) * 128 + o] * hv[u];
                }
            }
            #pragma unroll
            for (int j = 0; j < 4; ++j) {
                const int o = lane + 32 * j;
                g_h4[b][i][o] = fmaxf(b4[o] + ((acc[j][0] + acc[j][1]) + (acc[j][2] + acc[j][3])), 0.0f);
            }
        }
        __syncwarp();
    }
}

// ---------------- pool: smem w5 slice + f32x2 packed FMA + maxpool ----------------
// grid = BB * 4 quarters * 8 slots = 128 blocks of 256 threads; 1 output/thread.
#define PT 16
#define HSTRIDE 20
__global__ __launch_bounds__(256) void pool_kernel(const float* __restrict__ w5,
                                                   const float* __restrict__ b5) {
    extern __shared__ float psm[];
    float* ws = psm;                       // [128][257]
    float* hs = psm + 128 * 257;           // [128][HSTRIDE]
    const int bid = blockIdx.x;
    const int b = bid >> 5, q = (bid >> 3) & 3, slot = bid & 7;
    const int t = threadIdx.x;
    const int o = q * 256 + t;

    // stage w5 slice [128 k][256 o] transposed, conflict-free (stride 257)
    for (int c = 0; c < 128; ++c) {
        const int o2 = c * 2 + (t >> 7);
        const int k = t & 127;
        ws[k * 257 + o2] = w5[(q * 256 + o2) * 128 + k];
    }
    const int cnt = g_list_cnt[b];
    const float bias = b5[o];
    float rmax = 0.0f;

    for (int i0 = slot * PT; i0 < cnt; i0 += 8 * PT) {
        const int rem = min(PT, cnt - i0);
        __syncthreads();
        #pragma unroll
        for (int j = 0; j < 8; ++j) {
            const int idx = t + j * 256;
            const int p = idx >> 7, k = idx & 127;
            hs[k * HSTRIDE + p] = (p < rem) ? g_h4[b][i0 + p][k] : 0.0f;
        }
        __syncthreads();

        unsigned long long acc2[8];
        #pragma unroll
        for (int pp = 0; pp < 8; ++pp) acc2[pp] = 0ull;

        #pragma unroll 4
        for (int k = 0; k < 128; ++k) {
            const float wv = ws[k * 257 + t];
            unsigned long long wv2;
            asm("mov.b64 %0, {%1, %1};" : "=l"(wv2) : "r"(__float_as_uint(wv)));
            const float4* hp = (const float4*)(hs + k * HSTRIDE);   // 16B aligned (80B rows)
            #pragma unroll
            for (int u = 0; u < 4; ++u) {
                float4 h4v = hp[u];
                unsigned long long lo, hi;
                asm("mov.b64 %0, {%1, %2};" : "=l"(lo) : "r"(__float_as_uint(h4v.x)), "r"(__float_as_uint(h4v.y)));
                asm("mov.b64 %0, {%1, %2};" : "=l"(hi) : "r"(__float_as_uint(h4v.z)), "r"(__float_as_uint(h4v.w)));
                ffma2(acc2[2 * u],     wv2, lo);
                ffma2(acc2[2 * u + 1], wv2, hi);
            }
        }
        for (int p = 0; p < rem; ++p) {
            const unsigned long long a = acc2[p >> 1];
            const float av = __uint_as_float((p & 1) ? (unsigned)(a >> 32) : (unsigned)a);
            rmax = fmaxf(rmax, fmaxf(av + bias, 0.0f));
        }
    }
    atomicMax((unsigned int*)&g_feat[b * 1024 + o], __float_as_uint(rmax));
}

// ---------------- FC layer 1 (1024->512), one output per warp ---------------------
__global__ __launch_bounds__(256) void fc1_kernel(const float* __restrict__ fw1,
                                                  const float* __restrict__ fb1) {
    const int b = blockIdx.x >> 6, seg = blockIdx.x & 63;
    __shared__ __align__(16) float g[1024];
    const int t = threadIdx.x, w = t >> 5, lane = t & 31;

    for (int i = t; i < 1024; i += 256) g[i] = g_feat[b * 1024 + i];
    __syncthreads();

    const int o = seg * 8 + w;
    const float4* wr = (const float4*)(fw1 + o * 1024);
    float s = 0.0f;
    #pragma unroll
    for (int it = 0; it < 8; ++it) {
        float4 wv = wr[it * 32 + lane];
        float4 gv = *(const float4*)(g + it * 128 + lane * 4);
        s += wv.x * gv.x + wv.y * gv.y + wv.z * gv.z + wv.w * gv.w;
    }
    s = warp_sum(s);
    if (lane == 0) g_a1[b][o] = fmaxf(s + fb1[o], 0.0f);
}

// ---------------- FC layers 2+3 (512->256->3), 1 block per batch ------------------
__global__ __launch_bounds__(512) void fc2_kernel(
    const float* __restrict__ fw2, const float* __restrict__ fb2,
    const float* __restrict__ fw3, const float* __restrict__ fb3,
    float* __restrict__ out) {
    const int b = blockIdx.x;
    __shared__ __align__(16) float a1[512];
    __shared__ __align__(16) float a2[256];
    const int t = threadIdx.x, w = t >> 5, lane = t & 31;

    a1[t] = g_a1[b][t];
    __syncthreads();

    {
        const int o = w * 16;
        for (int j = 0; j < 16; ++j) {
            const float4* wr = (const float4*)(fw2 + (o + j) * 512);
            float s = 0.0f;
            #pragma unroll
            for (int it = 0; it < 4; ++it) {
                float4 wv = wr[it * 32 + lane];
                float4 av = *(const float4*)(a1 + it * 128 + lane * 4);
                s += wv.x * av.x + wv.y * av.y + wv.z * av.z + wv.w * av.w;
            }
            s = warp_sum(s);
            if (lane == 0) a2[o + j] = fmaxf(s + fb2[o + j], 0.0f);
        }
    }
    __syncthreads();

    if (w < 3) {
        const float4* wr = (const float4*)(fw3 + w * 256);
        float s = 0.0f;
        #pragma unroll
        for (int it = 0; it < 2; ++it) {
            float4 wv = wr[it * 32 + lane];
            float4 av = *(const float4*)(a2 + it * 128 + lane * 4);
            s += wv.x * av.x + wv.y * av.y + wv.z * av.z + wv.w * av.w;
        }
        s = warp_sum(s);
        if (lane == 0) out[b * 3 + w] = s + fb3[w];
    }
}

// ---------------- launch ----------------
extern "C" void kernel_launch(void* const* d_in, const int* in_sizes, int n_in,
                              void* d_out, int out_size) {
    const float* x   = (const float*)d_in[0];
    const int*   far = (const int*)  d_in[1];
    const float* w1 = (const float*)d_in[2];   const float* b1 = (const float*)d_in[3];
    const float* w2 = (const float*)d_in[4];   const float* b2 = (const float*)d_in[5];
    const float* w3 = (const float*)d_in[6];   const float* b3 = (const float*)d_in[7];
    const float* w4 = (const float*)d_in[8];   const float* b4 = (const float*)d_in[9];
    const float* w5 = (const float*)d_in[10];  const float* b5 = (const float*)d_in[11];
    const float* fw1 = (const float*)d_in[12]; const float* fb1 = (const float*)d_in[13];
    const float* fw2 = (const float*)d_in[14]; const float* fb2 = (const float*)d_in[15];
    const float* fw3 = (const float*)d_in[16]; const float* fb3 = (const float*)d_in[17];
    float* out = (float*)d_out;

    const int smem_fps  = 3 * NN * 4 + 1024 * 8;               // 204800
    const int smem_pool = 128 * 257 * 4 + 128 * HSTRIDE * 4;   // 141824
    static int attr_set = 0;
    if (!attr_set) {
        cudaFuncSetAttribute(fpsknn_kernel,
                             cudaFuncAttributeMaxDynamicSharedMemorySize, smem_fps);
        cudaFuncSetAttribute(pool_kernel,
                             cudaFuncAttributeMaxDynamicSharedMemorySize, smem_pool);
        attr_set = 1;
    }

    prep_kernel<<<32, 256>>>(w1, w2, w3, w4);
    fpsknn_kernel<<<BB * 16, 1024, smem_fps>>>(x, far);
    chain_kernel<<<BB * 16, 256>>>(x, b1, b2, b3, b4);
    pool_kernel<<<BB * 32, 256, smem_pool>>>(w5, b5);
    fc1_kernel<<<BB * 64, 256>>>(fw1, fb1);
    fc2_kernel<<<BB, 512>>>(fw2, fb2, fw3, fb3, out);
}

// round 9
// speedup vs baseline: 1.6365x; 1.0036x over previous
#include <cuda_runtime.h>

#define BB 4
#define NN 16384
#define NC 1024

// ---------------- scratch (device globals; no allocation allowed) ----------------
__device__ unsigned int g_flagbits[BB][NN / 32];
__device__ int          g_list[BB][NN];
__device__ int          g_list_cnt[BB];
__device__ float        g_feat[BB * 1024];           // max-pooled (relu'd) features
__device__ float        g_a1[BB][512];               // fc layer-1 activations
__device__ float        g_tw1[3 * 64];               // transposed small weights
__device__ float        g_tw2[64 * 64];
__device__ float        g_tw3[64 * 64];
__device__ float        g_tw4[64 * 128];
__device__ float        g_w5t[128 * 1024];           // transposed w5: [k][o]

// ---------------- helpers ----------------
__device__ __forceinline__ unsigned sortable(float d) {
    unsigned u = __float_as_uint(d);
    return (u & 0x80000000u) ? ~u : (u | 0x80000000u);   // ascending-sortable
}

__device__ __forceinline__ float warp_sum(float s) {
    #pragma unroll
    for (int off = 16; off; off >>= 1)
        s += __shfl_xor_sync(0xffffffffu, s, off);
    return s;
}

__device__ __forceinline__ unsigned long long u64max_bfly(unsigned long long v) {
    #pragma unroll
    for (int off = 16; off; off >>= 1) {
        unsigned long long v2 = __shfl_xor_sync(0xffffffffu, v, off);
        if (v2 > v) v = v2;
    }
    return v;
}

__device__ __forceinline__ void ffma2(unsigned long long& acc, unsigned long long a,
                                      unsigned long long b) {
    asm("fma.rn.f32x2 %0, %1, %2, %0;" : "+l"(acc) : "l"(a), "l"(b));
}

// ---------------- prep: w5 transpose (blocks 0-127) + zero/small (128-159) --------
__global__ __launch_bounds__(256) void prep_kernel(
    const float* __restrict__ w1, const float* __restrict__ w2,
    const float* __restrict__ w3, const float* __restrict__ w4,
    const float* __restrict__ w5) {
    const int t = threadIdx.x;
    if (blockIdx.x < 128) {
        __shared__ float tile[32][33];
        const int k0 = (blockIdx.x & 3) * 32;
        const int o0 = (blockIdx.x >> 2) * 32;
        const int tx = t & 31, ty = t >> 5;
        #pragma unroll
        for (int r = ty; r < 32; r += 8)
            tile[r][tx] = w5[(o0 + r) * 128 + k0 + tx];     // coalesced read
        __syncthreads();
        #pragma unroll
        for (int r = ty; r < 32; r += 8)
            g_w5t[(k0 + r) * 1024 + o0 + tx] = tile[tx][r]; // coalesced write
    } else {
        int i = (blockIdx.x - 128) * 256 + t;               // 0..8191
        if (i < BB * NN / 32) ((unsigned*)g_flagbits)[i] = 0u;
        if (i < BB * 1024)    g_feat[i] = 0.0f;
        if (i < BB)           g_list_cnt[i] = 0;
        if (i < 192)  { int o = i % 64, k = i / 64;  g_tw1[k * 64 + o]  = w1[o * 3 + k]; }
        if (i < 4096) { int o = i & 63, k = i >> 6;  g_tw2[k * 64 + o]  = w2[o * 64 + k];
                                                     g_tw3[k * 64 + o]  = w3[o * 64 + k]; }
        if (i < 8192) { int o = i & 127, k = i >> 7; g_tw4[k * 128 + o] = w4[o * 64 + k]; }
    }
}

// ---------------- fused FPS walk + exact radix top-32 KNN + dedup append ----------
__global__ __launch_bounds__(1024) void fpsknn_kernel(const float* __restrict__ x,
                                                      const int* __restrict__ far_init) {
    extern __shared__ float dsm[];
    float* sx = dsm;
    float* sy = sx + NN;
    float* sz = sy + NN;
    unsigned long long* cand = (unsigned long long*)(sz + NN);
    __shared__ unsigned long long s_pack[32];
    __shared__ unsigned s_seen[NN / 32];
    __shared__ int s_cent[NC];
    __shared__ int s_stop, s_cnt;
    __shared__ unsigned s_minidx;

    const int b = blockIdx.x >> 4, m0 = blockIdx.x & 15;
    const float* xb = x + (size_t)b * NN * 3;
    const int t = threadIdx.x, w = t >> 5, lane = t & 31;
    const unsigned lmask_lt = (1u << lane) - 1u;

    float rx[16], ry[16], rz[16];
    #pragma unroll
    for (int j = 0; j < 16; ++j) {
        const int i = t + j * 1024;
        float a = xb[i * 3 + 0], bv = xb[i * 3 + 1], c = xb[i * 3 + 2];
        sx[i] = a; sy[i] = bv; sz[i] = c;
        rx[j] = a; ry[j] = bv; rz[j] = c;
    }
    if (t < NN / 32) s_seen[t] = 0;
    if (t == 0) s_cnt = 0;
    __syncthreads();

    // ---- FPS walk with cycle detection (points in registers, 2 BARs/iter) ----
    int far = far_init[b];
    for (int it = 0; it < NC; ++it) {
        if (t == 0) {
            const unsigned wd = (unsigned)far >> 5, bt = 1u << (far & 31);
            if (s_seen[wd] & bt) { s_stop = 1; }
            else { s_seen[wd] |= bt; s_cent[s_cnt++] = far; s_stop = 0; }
        }
        __syncthreads();
        if (s_stop) break;
        if (it == NC - 1) break;

        const float cx = sx[far], cy = sy[far], cz = sz[far];
        float best = -1.0f; int bi = 0;
        #pragma unroll
        for (int j = 0; j < 16; ++j) {
            float dx = rx[j] - cx, dy = ry[j] - cy, dz = rz[j] - cz;
            float d = dx * dx + dy * dy + dz * dz;
            if (d > best) { best = d; bi = t + j * 1024; }   // strict >: lowest idx on tie
        }
        unsigned long long pk = ((unsigned long long)__float_as_uint(best) << 32)
                              | (unsigned)(~bi);
        pk = u64max_bfly(pk);
        if (lane == 0) s_pack[w] = pk;
        __syncthreads();
        unsigned long long v = s_pack[lane];
        v = u64max_bfly(v);
        far = (int)(~(unsigned)v);
    }
    __syncthreads();

    // ---- exact top-32 KNN via two-level radix select ----
    const int cnt = s_cnt;
    for (int m = m0; m < cnt; m += 16) {
        const int ci = s_cent[m];
        const float cx = sx[ci], cy = sy[ci], cz = sz[ci];
        const float cn = cx * cx + cy * cy + cz * cz;
        const int base = w * 512;

        unsigned ds[16];
        #pragma unroll
        for (int j = 0; j < 16; ++j) {
            const int p = base + j * 32 + lane;
            float px = sx[p], py = sy[p], pz = sz[p];
            float xn = px * px + py * py + pz * pz;
            float dot = cx * px + cy * py + cz * pz;
            ds[j] = sortable((cn + xn) - 2.0f * dot);
        }

        unsigned pfx = 0; int kth = 32;
        for (int bit = 31; bit >= 0; --bit) {
            const unsigned tgt = pfx << 1;
            int c = 0;
            #pragma unroll
            for (int j = 0; j < 16; ++j) c += ((ds[j] >> bit) == tgt);
            const int tot = __reduce_add_sync(0xffffffffu, c);
            if (kth <= tot) pfx = tgt; else { kth -= tot; pfx = tgt + 1; }
        }
        const unsigned T = pfx;

        unsigned selbits = 0;
        int cl = 0;
        #pragma unroll
        for (int j = 0; j < 16; ++j) {
            if (ds[j] < T) { selbits |= 1u << j; ++cl; }
        }
        int mtake = 32 - __reduce_add_sync(0xffffffffu, cl);
        while (mtake > 0) {
            unsigned me = 0xffffffffu; int jmin = -1;
            #pragma unroll
            for (int j = 0; j < 16; ++j) {
                if (ds[j] == T && !((selbits >> j) & 1u)) {
                    unsigned pid = (unsigned)(base + j * 32 + lane);
                    if (pid < me) { me = pid; jmin = j; }
                }
            }
            const unsigned gmin = __reduce_min_sync(0xffffffffu, me);
            if (me == gmin && jmin >= 0) selbits |= 1u << jmin;
            --mtake;
        }

        int off = 0;
        #pragma unroll
        for (int j = 0; j < 16; ++j) {
            const bool s = (selbits >> j) & 1u;
            const unsigned msk = __ballot_sync(0xffffffffu, s);
            if (s) {
                const int pos = off + __popc(msk & lmask_lt);
                cand[w * 32 + pos] = ((unsigned long long)ds[j] << 32)
                                   | (unsigned)(base + j * 32 + lane);
            }
            off += __popc(msk);
        }
        __syncthreads();

        const unsigned long long ck = cand[t];
        const unsigned cd = (unsigned)(ck >> 32);
        const unsigned cidx = (unsigned)ck;
        unsigned qfx = 0; int kb = 32;
        for (int bit = 31; bit >= 0; --bit) {
            const unsigned tgt = qfx << 1;
            const int c1 = __syncthreads_count((cd >> bit) == tgt);
            if (kb <= c1) qfx = tgt; else { kb -= c1; qfx = tgt + 1; }
        }
        const unsigned Tb = qfx;
        const int Lb = __syncthreads_count(cd < Tb);
        int mtk = 32 - Lb;
        bool takeme = (cd < Tb);
        while (mtk > 0) {
            if (t == 0) s_minidx = 0xffffffffu;
            __syncthreads();
            if (cd == Tb && !takeme) atomicMin(&s_minidx, cidx);
            __syncthreads();
            if (cd == Tb && !takeme && cidx == s_minidx) takeme = true;
            --mtk;
            __syncthreads();
        }
        if (takeme) {
            const int n = (int)cidx;
            const unsigned bt = 1u << (n & 31);
            unsigned old = atomicOr(&g_flagbits[b][(unsigned)n >> 5], bt);
            if (!(old & bt)) {
                int pos = atomicAdd(&g_list_cnt[b], 1);
                g_list[b][pos] = n;
            }
        }
        __syncthreads();
    }
}

// ---------------- fused chain+pool: per-point MLP in smem, w5t from L2, maxpool ---
// Grid: BB * 4 quarters * 8 slots = 128 blocks of 512 threads.
// Phase 1: warp p computes the 3->64->64->64->128 chain for point i0+p into hs[k][p].
// Phase 2: threads 0-255 each own output o = q*256+t; packed f32x2 FMA over 16 pts.
#define PT 16
__global__ __launch_bounds__(512) void poolchain_kernel(
    const float* __restrict__ x,
    const float* __restrict__ b1, const float* __restrict__ b2,
    const float* __restrict__ b3, const float* __restrict__ b4,
    const float* __restrict__ b5) {
    __shared__ float sh[16][64];
    __shared__ float hs[128][PT];          // k-major; rows 64B -> LDS.128 aligned
    const int bid = blockIdx.x;
    const int b = bid >> 5, q = (bid >> 3) & 3, slot = bid & 7;
    const int t = threadIdx.x, w = t >> 5, lane = t & 31;
    const int cnt = g_list_cnt[b];

    const int o = q * 256 + (t & 255);
    const float bias = b5[o];
    float rmax = 0.0f;

    for (int i0 = slot * PT; i0 < cnt; i0 += 8 * PT) {
        const int rem = min(PT, cnt - i0);
        const int i = i0 + w;

        if (w >= rem) {
            // inactive warp: zero its hs column
            #pragma unroll
            for (int k = lane; k < 128; k += 32) hs[k][w] = 0.0f;
        } else {
            const int n = g_list[b][i];
            const float* pp = x + ((size_t)b * NN + n) * 3;
            const float px = pp[0], py = pp[1], pz = pp[2];
            const int oA = lane, oB = lane + 32;

            {
                float a = b1[oA] + g_tw1[oA] * px + g_tw1[64 + oA] * py + g_tw1[128 + oA] * pz;
                float c = b1[oB] + g_tw1[oB] * px + g_tw1[64 + oB] * py + g_tw1[128 + oB] * pz;
                sh[w][oA] = fmaxf(a, 0.0f);
                sh[w][oB] = fmaxf(c, 0.0f);
            }
            __syncwarp();
            {
                float A0 = 0.f, A1 = 0.f, A2 = 0.f, A3 = 0.f;
                float B0 = 0.f, B1 = 0.f, B2 = 0.f, B3 = 0.f;
                #pragma unroll
                for (int k = 0; k < 64; k += 4) {
                    float h0 = sh[w][k], h1 = sh[w][k + 1], h2 = sh[w][k + 2], h3 = sh[w][k + 3];
                    A0 += g_tw2[(k + 0) * 64 + oA] * h0; A1 += g_tw2[(k + 1) * 64 + oA] * h1;
                    A2 += g_tw2[(k + 2) * 64 + oA] * h2; A3 += g_tw2[(k + 3) * 64 + oA] * h3;
                    B0 += g_tw2[(k + 0) * 64 + oB] * h0; B1 += g_tw2[(k + 1) * 64 + oB] * h1;
                    B2 += g_tw2[(k + 2) * 64 + oB] * h2; B3 += g_tw2[(k + 3) * 64 + oB] * h3;
                }
                float ha = fmaxf(b2[oA] + ((A0 + A1) + (A2 + A3)), 0.0f);
                float hb = fmaxf(b2[oB] + ((B0 + B1) + (B2 + B3)), 0.0f);
                __syncwarp();
                sh[w][oA] = ha; sh[w][oB] = hb;
            }
            __syncwarp();
            {
                float A0 = 0.f, A1 = 0.f, A2 = 0.f, A3 = 0.f;
                float B0 = 0.f, B1 = 0.f, B2 = 0.f, B3 = 0.f;
                #pragma unroll
                for (int k = 0; k < 64; k += 4) {
                    float h0 = sh[w][k], h1 = sh[w][k + 1], h2 = sh[w][k + 2], h3 = sh[w][k + 3];
                    A0 += g_tw3[(k + 0) * 64 + oA] * h0; A1 += g_tw3[(k + 1) * 64 + oA] * h1;
                    A2 += g_tw3[(k + 2) * 64 + oA] * h2; A3 += g_tw3[(k + 3) * 64 + oA] * h3;
                    B0 += g_tw3[(k + 0) * 64 + oB] * h0; B1 += g_tw3[(k + 1) * 64 + oB] * h1;
                    B2 += g_tw3[(k + 2) * 64 + oB] * h2; B3 += g_tw3[(k + 3) * 64 + oB] * h3;
                }
                float ha = fmaxf(b3[oA] + ((A0 + A1) + (A2 + A3)), 0.0f);
                float hb = fmaxf(b3[oB] + ((B0 + B1) + (B2 + B3)), 0.0f);
                __syncwarp();
                sh[w][oA] = ha; sh[w][oB] = hb;
            }
            __syncwarp();
            {
                float acc[4][4];
                #pragma unroll
                for (int j = 0; j < 4; ++j)
                    #pragma unroll
                    for (int u = 0; u < 4; ++u) acc[j][u] = 0.f;
                #pragma unroll
                for (int k = 0; k < 64; k += 4) {
                    float hv[4] = {sh[w][k], sh[w][k + 1], sh[w][k + 2], sh[w][k + 3]};
                    #pragma unroll
                    for (int j = 0; j < 4; ++j) {
                        const int oo = lane + 32 * j;
                        #pragma unroll
                        for (int u = 0; u < 4; ++u)
                            acc[j][u] += g_tw4[(k + u) * 128 + oo] * hv[u];
                    }
                }
                #pragma unroll
                for (int j = 0; j < 4; ++j) {
                    const int oo = lane + 32 * j;
                    hs[oo][w] = fmaxf(b4[oo] + ((acc[j][0] + acc[j][1]) + (acc[j][2] + acc[j][3])), 0.0f);
                }
            }
        }
        __syncthreads();

        // ---- pool phase: threads 0-255, packed f32x2, w5t coalesced from L2 ----
        if (t < 256) {
            unsigned long long acc2[8];
            #pragma unroll
            for (int pp = 0; pp < 8; ++pp) acc2[pp] = 0ull;

            const float* wtp = g_w5t + o;
            #pragma unroll 4
            for (int k = 0; k < 128; ++k) {
                const float wv = wtp[k * 1024];
                unsigned long long wv2;
                asm("mov.b64 %0, {%1, %1};" : "=l"(wv2) : "r"(__float_as_uint(wv)));
                const float4* hp = (const float4*)(hs[k]);
                #pragma unroll
                for (int u = 0; u < 4; ++u) {
                    float4 h4v = hp[u];
                    unsigned long long lo, hi;
                    asm("mov.b64 %0, {%1, %2};" : "=l"(lo) : "r"(__float_as_uint(h4v.x)), "r"(__float_as_uint(h4v.y)));
                    asm("mov.b64 %0, {%1, %2};" : "=l"(hi) : "r"(__float_as_uint(h4v.z)), "r"(__float_as_uint(h4v.w)));
                    ffma2(acc2[2 * u],     wv2, lo);
                    ffma2(acc2[2 * u + 1], wv2, hi);
                }
            }
            for (int p = 0; p < rem; ++p) {
                const unsigned long long a = acc2[p >> 1];
                const float av = __uint_as_float((p & 1) ? (unsigned)(a >> 32) : (unsigned)a);
                rmax = fmaxf(rmax, fmaxf(av + bias, 0.0f));
            }
        }
        __syncthreads();   // protect hs before next chunk's chain writes
    }

    if (t < 256)
        atomicMax((unsigned int*)&g_feat[b * 1024 + o], __float_as_uint(rmax));
}

// ---------------- FC layer 1 (1024->512), one output per warp ---------------------
__global__ __launch_bounds__(256) void fc1_kernel(const float* __restrict__ fw1,
                                                  const float* __restrict__ fb1) {
    const int b = blockIdx.x >> 6, seg = blockIdx.x & 63;
    __shared__ __align__(16) float g[1024];
    const int t = threadIdx.x, w = t >> 5, lane = t & 31;

    for (int i = t; i < 1024; i += 256) g[i] = g_feat[b * 1024 + i];
    __syncthreads();

    const int o = seg * 8 + w;
    const float4* wr = (const float4*)(fw1 + o * 1024);
    float s = 0.0f;
    #pragma unroll
    for (int it = 0; it < 8; ++it) {
        float4 wv = wr[it * 32 + lane];
        float4 gv = *(const float4*)(g + it * 128 + lane * 4);
        s += wv.x * gv.x + wv.y * gv.y + wv.z * gv.z + wv.w * gv.w;
    }
    s = warp_sum(s);
    if (lane == 0) g_a1[b][o] = fmaxf(s + fb1[o], 0.0f);
}

// ---------------- FC layers 2+3 (512->256->3), 1 block per batch ------------------
__global__ __launch_bounds__(512) void fc2_kernel(
    const float* __restrict__ fw2, const float* __restrict__ fb2,
    const float* __restrict__ fw3, const float* __restrict__ fb3,
    float* __restrict__ out) {
    const int b = blockIdx.x;
    __shared__ __align__(16) float a1[512];
    __shared__ __align__(16) float a2[256];
    const int t = threadIdx.x, w = t >> 5, lane = t & 31;

    a1[t] = g_a1[b][t];
    __syncthreads();

    {
        const int o = w * 16;
        for (int j = 0; j < 16; ++j) {
            const float4* wr = (const float4*)(fw2 + (o + j) * 512);
            float s = 0.0f;
            #pragma unroll
            for (int it = 0; it < 4; ++it) {
                float4 wv = wr[it * 32 + lane];
                float4 av = *(const float4*)(a1 + it * 128 + lane * 4);
                s += wv.x * av.x + wv.y * av.y + wv.z * av.z + wv.w * av.w;
            }
            s = warp_sum(s);
            if (lane == 0) a2[o + j] = fmaxf(s + fb2[o + j], 0.0f);
        }
    }
    __syncthreads();

    if (w < 3) {
        const float4* wr = (const float4*)(fw3 + w * 256);
        float s = 0.0f;
        #pragma unroll
        for (int it = 0; it < 2; ++it) {
            float4 wv = wr[it * 32 + lane];
            float4 av = *(const float4*)(a2 + it * 128 + lane * 4);
            s += wv.x * av.x + wv.y * av.y + wv.z * av.z + wv.w * av.w;
        }
        s = warp_sum(s);
        if (lane == 0) out[b * 3 + w] = s + fb3[w];
    }
}

// ---------------- launch ----------------
extern "C" void kernel_launch(void* const* d_in, const int* in_sizes, int n_in,
                              void* d_out, int out_size) {
    const float* x   = (const float*)d_in[0];
    const int*   far = (const int*)  d_in[1];
    const float* w1 = (const float*)d_in[2];   const float* b1 = (const float*)d_in[3];
    const float* w2 = (const float*)d_in[4];   const float* b2 = (const float*)d_in[5];
    const float* w3 = (const float*)d_in[6];   const float* b3 = (const float*)d_in[7];
    const float* w4 = (const float*)d_in[8];   const float* b4 = (const float*)d_in[9];
    const float* w5 = (const float*)d_in[10];  const float* b5 = (const float*)d_in[11];
    const float* fw1 = (const float*)d_in[12]; const float* fb1 = (const float*)d_in[13];
    const float* fw2 = (const float*)d_in[14]; const float* fb2 = (const float*)d_in[15];
    const float* fw3 = (const float*)d_in[16]; const float* fb3 = (const float*)d_in[17];
    float* out = (float*)d_out;

    const int smem_fps = 3 * NN * 4 + 1024 * 8;               // 204800
    static int attr_set = 0;
    if (!attr_set) {
        cudaFuncSetAttribute(fpsknn_kernel,
                             cudaFuncAttributeMaxDynamicSharedMemorySize, smem_fps);
        attr_set = 1;
    }

    prep_kernel<<<160, 256>>>(w1, w2, w3, w4, w5);
    fpsknn_kernel<<<BB * 16, 1024, smem_fps>>>(x, far);
    poolchain_kernel<<<BB * 32, 512>>>(x, b1, b2, b3, b4, b5);
    fc1_kernel<<<BB * 64, 256>>>(fw1, fb1);
    fc2_kernel<<<BB, 512>>>(fw2, fb2, fw3, fb3, out);
}

// round 10
// speedup vs baseline: 1.7251x; 1.0541x over previous
#include <cuda_runtime.h>

#define BB 4
#define NN 16384
#define NC 1024

// ---------------- scratch (device globals; no allocation allowed) ----------------
__device__ unsigned int g_flagbits[BB][NN / 32];
__device__ int          g_list[BB][NN];
__device__ int          g_list_cnt[BB];
__device__ float        g_feat[BB * 1024];           // max-pooled (relu'd) features
__device__ float        g_a1[BB][512];               // fc layer-1 activations
__device__ float        g_tw1[3 * 64];               // transposed small weights
__device__ float        g_tw2[64 * 64];
__device__ float        g_tw3[64 * 64];
__device__ float        g_tw4[64 * 128];
__device__ float        g_w5t[128 * 1024];           // transposed w5: [k][o]

// ---------------- helpers ----------------
__device__ __forceinline__ unsigned sortable(float d) {
    unsigned u = __float_as_uint(d);
    return (u & 0x80000000u) ? ~u : (u | 0x80000000u);   // ascending-sortable
}

__device__ __forceinline__ float warp_sum(float s) {
    #pragma unroll
    for (int off = 16; off; off >>= 1)
        s += __shfl_xor_sync(0xffffffffu, s, off);
    return s;
}

__device__ __forceinline__ void ffma2(unsigned long long& acc, unsigned long long a,
                                      unsigned long long b) {
    asm("fma.rn.f32x2 %0, %1, %2, %0;" : "+l"(acc) : "l"(a), "l"(b));
}

// ---------------- prep: w5 transpose (blocks 0-127) + zero/small (128-159) --------
__global__ __launch_bounds__(256) void prep_kernel(
    const float* __restrict__ w1, const float* __restrict__ w2,
    const float* __restrict__ w3, const float* __restrict__ w4,
    const float* __restrict__ w5) {
    const int t = threadIdx.x;
    if (blockIdx.x < 128) {
        __shared__ float tile[32][33];
        const int k0 = (blockIdx.x & 3) * 32;
        const int o0 = (blockIdx.x >> 2) * 32;
        const int tx = t & 31, ty = t >> 5;
        #pragma unroll
        for (int r = ty; r < 32; r += 8)
            tile[r][tx] = w5[(o0 + r) * 128 + k0 + tx];     // coalesced read
        __syncthreads();
        #pragma unroll
        for (int r = ty; r < 32; r += 8)
            g_w5t[(k0 + r) * 1024 + o0 + tx] = tile[tx][r]; // coalesced write
    } else {
        int i = (blockIdx.x - 128) * 256 + t;               // 0..8191
        if (i < BB * NN / 32) ((unsigned*)g_flagbits)[i] = 0u;
        if (i < BB * 1024)    g_feat[i] = 0.0f;
        if (i < BB)           g_list_cnt[i] = 0;
        if (i < 192)  { int o = i % 64, k = i / 64;  g_tw1[k * 64 + o]  = w1[o * 3 + k]; }
        if (i < 4096) { int o = i & 63, k = i >> 6;  g_tw2[k * 64 + o]  = w2[o * 64 + k];
                                                     g_tw3[k * 64 + o]  = w3[o * 64 + k]; }
        if (i < 8192) { int o = i & 127, k = i >> 7; g_tw4[k * 128 + o] = w4[o * 64 + k]; }
    }
}

// ---------------- fused FPS walk + exact radix top-32 KNN + dedup append ----------
// BB*32 blocks of 1024; all co-resident (204.8KB smem -> 1 block/SM, 128 SMs).
__global__ __launch_bounds__(1024) void fpsknn_kernel(const float* __restrict__ x,
                                                      const int* __restrict__ far_init) {
    extern __shared__ float dsm[];
    float* sx = dsm;
    float* sy = sx + NN;
    float* sz = sy + NN;
    unsigned long long* cand = (unsigned long long*)(sz + NN);
    __shared__ unsigned s_du[2][32];
    __shared__ unsigned s_iu[2][32];
    __shared__ unsigned s_seen[NN / 32];
    __shared__ int s_cent[NC];
    __shared__ int s_stop, s_cnt;
    __shared__ unsigned s_minidx;

    const int b = blockIdx.x >> 5, m0 = blockIdx.x & 31;
    const float* xb = x + (size_t)b * NN * 3;
    const int t = threadIdx.x, w = t >> 5, lane = t & 31;
    const unsigned lmask_lt = (1u << lane) - 1u;

    float rx[16], ry[16], rz[16];
    #pragma unroll
    for (int j = 0; j < 16; ++j) {
        const int i = t + j * 1024;
        float a = xb[i * 3 + 0], bv = xb[i * 3 + 1], c = xb[i * 3 + 2];
        sx[i] = a; sy[i] = bv; sz[i] = c;
        rx[j] = a; ry[j] = bv; rz[j] = c;
    }
    if (t < NN / 32) s_seen[t] = 0;
    if (t == 0) s_cnt = 0;
    __syncthreads();

    // ---- FPS walk with cycle detection: REDUX argmax, 1 BAR/iter (double-buffered)
    int far = far_init[b];
    for (int it = 0; it < NC; ++it) {
        if (t == 0) {
            const unsigned wd = (unsigned)far >> 5, bt = 1u << (far & 31);
            if (s_seen[wd] & bt) { s_stop = 1; }
            else { s_seen[wd] |= bt; s_cent[s_cnt++] = far; s_stop = 0; }
        }
        const int pb = it & 1;
        __syncthreads();     // also publishes s_stop and protects s_du[pb] reuse
        if (s_stop) break;
        if (it == NC - 1) break;

        const float cx = sx[far], cy = sy[far], cz = sz[far];
        float best = -1.0f; int bi = 0;
        #pragma unroll
        for (int j = 0; j < 16; ++j) {
            float dx = rx[j] - cx, dy = ry[j] - cy, dz = rz[j] - cz;
            float d = dx * dx + dy * dy + dz * dz;
            if (d > best) { best = d; bi = t + j * 1024; }   // strict >: lowest idx on tie
        }
        // warp argmax: d >= 0 so float bits are monotone
        const unsigned db = __float_as_uint(best);
        const unsigned dmax = __reduce_max_sync(0xffffffffu, db);
        const unsigned im = (db == dmax) ? (unsigned)bi : 0xffffffffu;
        const unsigned imin = __reduce_min_sync(0xffffffffu, im);
        if (lane == 0) { s_du[pb][w] = dmax; s_iu[pb][w] = imin; }
        __syncthreads();
        // block argmax: every warp reduces the 32 per-warp results redundantly
        const unsigned d2 = s_du[pb][lane];
        const unsigned i2 = s_iu[pb][lane];
        const unsigned dm2 = __reduce_max_sync(0xffffffffu, d2);
        const unsigned ii = (d2 == dm2) ? i2 : 0xffffffffu;
        far = (int)__reduce_min_sync(0xffffffffu, ii);
    }
    __syncthreads();

    // ---- exact top-32 KNN via two-level radix select ----
    const int cnt = s_cnt;
    for (int m = m0; m < cnt; m += 32) {
        const int ci = s_cent[m];
        const float cx = sx[ci], cy = sy[ci], cz = sz[ci];
        const float cn = cx * cx + cy * cy + cz * cz;
        const int base = w * 512;

        unsigned ds[16];
        #pragma unroll
        for (int j = 0; j < 16; ++j) {
            const int p = base + j * 32 + lane;
            float px = sx[p], py = sy[p], pz = sz[p];
            float xn = px * px + py * py + pz * pz;
            float dot = cx * px + cy * py + cz * pz;
            ds[j] = sortable((cn + xn) - 2.0f * dot);
        }

        unsigned pfx = 0; int kth = 32;
        for (int bit = 31; bit >= 0; --bit) {
            const unsigned tgt = pfx << 1;
            int c = 0;
            #pragma unroll
            for (int j = 0; j < 16; ++j) c += ((ds[j] >> bit) == tgt);
            const int tot = __reduce_add_sync(0xffffffffu, c);
            if (kth <= tot) pfx = tgt; else { kth -= tot; pfx = tgt + 1; }
        }
        const unsigned T = pfx;

        unsigned selbits = 0;
        int cl = 0;
        #pragma unroll
        for (int j = 0; j < 16; ++j) {
            if (ds[j] < T) { selbits |= 1u << j; ++cl; }
        }
        int mtake = 32 - __reduce_add_sync(0xffffffffu, cl);
        while (mtake > 0) {
            unsigned me = 0xffffffffu; int jmin = -1;
            #pragma unroll
            for (int j = 0; j < 16; ++j) {
                if (ds[j] == T && !((selbits >> j) & 1u)) {
                    unsigned pid = (unsigned)(base + j * 32 + lane);
                    if (pid < me) { me = pid; jmin = j; }
                }
            }
            const unsigned gmin = __reduce_min_sync(0xffffffffu, me);
            if (me == gmin && jmin >= 0) selbits |= 1u << jmin;
            --mtake;
        }

        int off = 0;
        #pragma unroll
        for (int j = 0; j < 16; ++j) {
            const bool s = (selbits >> j) & 1u;
            const unsigned msk = __ballot_sync(0xffffffffu, s);
            if (s) {
                const int pos = off + __popc(msk & lmask_lt);
                cand[w * 32 + pos] = ((unsigned long long)ds[j] << 32)
                                   | (unsigned)(base + j * 32 + lane);
            }
            off += __popc(msk);
        }
        __syncthreads();

        const unsigned long long ck = cand[t];
        const unsigned cd = (unsigned)(ck >> 32);
        const unsigned cidx = (unsigned)ck;
        unsigned qfx = 0; int kb = 32;
        for (int bit = 31; bit >= 0; --bit) {
            const unsigned tgt = qfx << 1;
            const int c1 = __syncthreads_count((cd >> bit) == tgt);
            if (kb <= c1) qfx = tgt; else { kb -= c1; qfx = tgt + 1; }
        }
        const unsigned Tb = qfx;
        const int Lb = __syncthreads_count(cd < Tb);
        int mtk = 32 - Lb;
        bool takeme = (cd < Tb);
        while (mtk > 0) {
            if (t == 0) s_minidx = 0xffffffffu;
            __syncthreads();
            if (cd == Tb && !takeme) atomicMin(&s_minidx, cidx);
            __syncthreads();
            if (cd == Tb && !takeme && cidx == s_minidx) takeme = true;
            --mtk;
            __syncthreads();
        }
        if (takeme) {
            const int n = (int)cidx;
            const unsigned bt = 1u << (n & 31);
            unsigned old = atomicOr(&g_flagbits[b][(unsigned)n >> 5], bt);
            if (!(old & bt)) {
                int pos = atomicAdd(&g_list_cnt[b], 1);
                g_list[b][pos] = n;
            }
        }
        __syncthreads();
    }
}

// ---------------- fused chain+pool: per-point MLP in smem, w5t from L2, maxpool ---
#define PT 16
__global__ __launch_bounds__(512) void poolchain_kernel(
    const float* __restrict__ x,
    const float* __restrict__ b1, const float* __restrict__ b2,
    const float* __restrict__ b3, const float* __restrict__ b4,
    const float* __restrict__ b5) {
    __shared__ float sh[16][64];
    __shared__ float hs[128][PT];          // k-major; rows 64B -> LDS.128 aligned
    const int bid = blockIdx.x;
    const int b = bid >> 5, q = (bid >> 3) & 3, slot = bid & 7;
    const int t = threadIdx.x, w = t >> 5, lane = t & 31;
    const int cnt = g_list_cnt[b];

    const int o = q * 256 + (t & 255);
    const float bias = b5[o];
    float rmax = 0.0f;

    for (int i0 = slot * PT; i0 < cnt; i0 += 8 * PT) {
        const int rem = min(PT, cnt - i0);
        const int i = i0 + w;

        if (w >= rem) {
            #pragma unroll
            for (int k = lane; k < 128; k += 32) hs[k][w] = 0.0f;
        } else {
            const int n = g_list[b][i];
            const float* pp = x + ((size_t)b * NN + n) * 3;
            const float px = pp[0], py = pp[1], pz = pp[2];
            const int oA = lane, oB = lane + 32;

            {
                float a = b1[oA] + g_tw1[oA] * px + g_tw1[64 + oA] * py + g_tw1[128 + oA] * pz;
                float c = b1[oB] + g_tw1[oB] * px + g_tw1[64 + oB] * py + g_tw1[128 + oB] * pz;
                sh[w][oA] = fmaxf(a, 0.0f);
                sh[w][oB] = fmaxf(c, 0.0f);
            }
            __syncwarp();
            {
                float A0 = 0.f, A1 = 0.f, A2 = 0.f, A3 = 0.f;
                float B0 = 0.f, B1 = 0.f, B2 = 0.f, B3 = 0.f;
                #pragma unroll
                for (int k = 0; k < 64; k += 4) {
                    float h0 = sh[w][k], h1 = sh[w][k + 1], h2 = sh[w][k + 2], h3 = sh[w][k + 3];
                    A0 += g_tw2[(k + 0) * 64 + oA] * h0; A1 += g_tw2[(k + 1) * 64 + oA] * h1;
                    A2 += g_tw2[(k + 2) * 64 + oA] * h2; A3 += g_tw2[(k + 3) * 64 + oA] * h3;
                    B0 += g_tw2[(k + 0) * 64 + oB] * h0; B1 += g_tw2[(k + 1) * 64 + oB] * h1;
                    B2 += g_tw2[(k + 2) * 64 + oB] * h2; B3 += g_tw2[(k + 3) * 64 + oB] * h3;
                }
                float ha = fmaxf(b2[oA] + ((A0 + A1) + (A2 + A3)), 0.0f);
                float hb = fmaxf(b2[oB] + ((B0 + B1) + (B2 + B3)), 0.0f);
                __syncwarp();
                sh[w][oA] = ha; sh[w][oB] = hb;
            }
            __syncwarp();
            {
                float A0 = 0.f, A1 = 0.f, A2 = 0.f, A3 = 0.f;
                float B0 = 0.f, B1 = 0.f, B2 = 0.f, B3 = 0.f;
                #pragma unroll
                for (int k = 0; k < 64; k += 4) {
                    float h0 = sh[w][k], h1 = sh[w][k + 1], h2 = sh[w][k + 2], h3 = sh[w][k + 3];
                    A0 += g_tw3[(k + 0) * 64 + oA] * h0; A1 += g_tw3[(k + 1) * 64 + oA] * h1;
                    A2 += g_tw3[(k + 2) * 64 + oA] * h2; A3 += g_tw3[(k + 3) * 64 + oA] * h3;
                    B0 += g_tw3[(k + 0) * 64 + oB] * h0; B1 += g_tw3[(k + 1) * 64 + oB] * h1;
                    B2 += g_tw3[(k + 2) * 64 + oB] * h2; B3 += g_tw3[(k + 3) * 64 + oB] * h3;
                }
                float ha = fmaxf(b3[oA] + ((A0 + A1) + (A2 + A3)), 0.0f);
                float hb = fmaxf(b3[oB] + ((B0 + B1) + (B2 + B3)), 0.0f);
                __syncwarp();
                sh[w][oA] = ha; sh[w][oB] = hb;
            }
            __syncwarp();
            {
                float acc[4][4];
                #pragma unroll
                for (int j = 0; j < 4; ++j)
                    #pragma unroll
                    for (int u = 0; u < 4; ++u) acc[j][u] = 0.f;
                #pragma unroll
                for (int k = 0; k < 64; k += 4) {
                    float hv[4] = {sh[w][k], sh[w][k + 1], sh[w][k + 2], sh[w][k + 3]};
                    #pragma unroll
                    for (int j = 0; j < 4; ++j) {
                        const int oo = lane + 32 * j;
                        #pragma unroll
                        for (int u = 0; u < 4; ++u)
                            acc[j][u] += g_tw4[(k + u) * 128 + oo] * hv[u];
                    }
                }
                #pragma unroll
                for (int j = 0; j < 4; ++j) {
                    const int oo = lane + 32 * j;
                    hs[oo][w] = fmaxf(b4[oo] + ((acc[j][0] + acc[j][1]) + (acc[j][2] + acc[j][3])), 0.0f);
                }
            }
        }
        __syncthreads();

        if (t < 256) {
            unsigned long long acc2[8];
            #pragma unroll
            for (int pp = 0; pp < 8; ++pp) acc2[pp] = 0ull;

            const float* wtp = g_w5t + o;
            #pragma unroll 4
            for (int k = 0; k < 128; ++k) {
                const float wv = wtp[k * 1024];
                unsigned long long wv2;
                asm("mov.b64 %0, {%1, %1};" : "=l"(wv2) : "r"(__float_as_uint(wv)));
                const float4* hp = (const float4*)(hs[k]);
                #pragma unroll
                for (int u = 0; u < 4; ++u) {
                    float4 h4v = hp[u];
                    unsigned long long lo, hi;
                    asm("mov.b64 %0, {%1, %2};" : "=l"(lo) : "r"(__float_as_uint(h4v.x)), "r"(__float_as_uint(h4v.y)));
                    asm("mov.b64 %0, {%1, %2};" : "=l"(hi) : "r"(__float_as_uint(h4v.z)), "r"(__float_as_uint(h4v.w)));
                    ffma2(acc2[2 * u],     wv2, lo);
                    ffma2(acc2[2 * u + 1], wv2, hi);
                }
            }
            for (int p = 0; p < rem; ++p) {
                const unsigned long long a = acc2[p >> 1];
                const float av = __uint_as_float((p & 1) ? (unsigned)(a >> 32) : (unsigned)a);
                rmax = fmaxf(rmax, fmaxf(av + bias, 0.0f));
            }
        }
        __syncthreads();
    }

    if (t < 256)
        atomicMax((unsigned int*)&g_feat[b * 1024 + o], __float_as_uint(rmax));
}

// ---------------- FC layer 1 (1024->512), one output per warp, prefetched ---------
__global__ __launch_bounds__(256) void fc1_kernel(const float* __restrict__ fw1,
                                                  const float* __restrict__ fb1) {
    const int b = blockIdx.x >> 6, seg = blockIdx.x & 63;
    __shared__ __align__(16) float g[1024];
    const int t = threadIdx.x, w = t >> 5, lane = t & 31;

    for (int i = t; i < 1024; i += 256) g[i] = g_feat[b * 1024 + i];

    const int o = seg * 8 + w;
    const float4* wr = (const float4*)(fw1 + o * 1024);
    float4 wv[8];
    #pragma unroll
    for (int it = 0; it < 8; ++it) wv[it] = wr[it * 32 + lane];   // 8 LDGs in flight

    __syncthreads();
    float s = 0.0f;
    #pragma unroll
    for (int it = 0; it < 8; ++it) {
        float4 gv = *(const float4*)(g + it * 128 + lane * 4);
        s += wv[it].x * gv.x + wv[it].y * gv.y + wv[it].z * gv.z + wv[it].w * gv.w;
    }
    s = warp_sum(s);
    if (lane == 0) g_a1[b][o] = fmaxf(s + fb1[o], 0.0f);
}

// ---------------- FC layers 2+3 (512->256->3), 1 block per batch ------------------
__global__ __launch_bounds__(512) void fc2_kernel(
    const float* __restrict__ fw2, const float* __restrict__ fb2,
    const float* __restrict__ fw3, const float* __restrict__ fb3,
    float* __restrict__ out) {
    const int b = blockIdx.x;
    __shared__ __align__(16) float a1[512];
    __shared__ __align__(16) float a2[256];
    const int t = threadIdx.x, w = t >> 5, lane = t & 31;

    a1[t] = g_a1[b][t];
    __syncthreads();

    {
        const int o = w * 16;
        for (int j = 0; j < 16; ++j) {
            const float4* wr = (const float4*)(fw2 + (o + j) * 512);
            float s = 0.0f;
            #pragma unroll
            for (int it = 0; it < 4; ++it) {
                float4 wv = wr[it * 32 + lane];
                float4 av = *(const float4*)(a1 + it * 128 + lane * 4);
                s += wv.x * av.x + wv.y * av.y + wv.z * av.z + wv.w * av.w;
            }
            s = warp_sum(s);
            if (lane == 0) a2[o + j] = fmaxf(s + fb2[o + j], 0.0f);
        }
    }
    __syncthreads();

    if (w < 3) {
        const float4* wr = (const float4*)(fw3 + w * 256);
        float s = 0.0f;
        #pragma unroll
        for (int it = 0; it < 2; ++it) {
            float4 wv = wr[it * 32 + lane];
            float4 av = *(const float4*)(a2 + it * 128 + lane * 4);
            s += wv.x * av.x + wv.y * av.y + wv.z * av.z + wv.w * av.w;
        }
        s = warp_sum(s);
        if (lane == 0) out[b * 3 + w] = s + fb3[w];
    }
}

// ---------------- launch ----------------
extern "C" void kernel_launch(void* const* d_in, const int* in_sizes, int n_in,
                              void* d_out, int out_size) {
    const float* x   = (const float*)d_in[0];
    const int*   far = (const int*)  d_in[1];
    const float* w1 = (const float*)d_in[2];   const float* b1 = (const float*)d_in[3];
    const float* w2 = (const float*)d_in[4];   const float* b2 = (const float*)d_in[5];
    const float* w3 = (const float*)d_in[6];   const float* b3 = (const float*)d_in[7];
    const float* w4 = (const float*)d_in[8];   const float* b4 = (const float*)d_in[9];
    const float* w5 = (const float*)d_in[10];  const float* b5 = (const float*)d_in[11];
    const float* fw1 = (const float*)d_in[12]; const float* fb1 = (const float*)d_in[13];
    const float* fw2 = (const float*)d_in[14]; const float* fb2 = (const float*)d_in[15];
    const float* fw3 = (const float*)d_in[16]; const float* fb3 = (const float*)d_in[17];
    float* out = (float*)d_out;

    const int smem_fps = 3 * NN * 4 + 1024 * 8;               // 204800
    static int attr_set = 0;
    if (!attr_set) {
        cudaFuncSetAttribute(fpsknn_kernel,
                             cudaFuncAttributeMaxDynamicSharedMemorySize, smem_fps);
        attr_set = 1;
    }

    prep_kernel<<<160, 256>>>(w1, w2, w3, w4, w5);
    fpsknn_kernel<<<BB * 32, 1024, smem_fps>>>(x, far);
    poolchain_kernel<<<BB * 32, 512>>>(x, b1, b2, b3, b4, b5);
    fc1_kernel<<<BB * 64, 256>>>(fw1, fb1);
    fc2_kernel<<<BB, 512>>>(fw2, fb2, fw3, fb3, out);
}